// round 1
// baseline (speedup 1.0000x reference)
#include <cuda_runtime.h>
#include <math.h>

#define B 4
#define C 64
#define CQK 128
#define HDIM 256
#define WDIM 256
#define HW 65536
#define HEADS 8

// ---------------- scratch (device globals; no allocations allowed) ----------
__device__ float g_qk_pre[(size_t)B * CQK * HW];  // qkv pre-depthwise, q+k only
__device__ float g_y[(size_t)B * C * HW];         // BN(m1(x))
__device__ float g_qk[(size_t)B * CQK * HW];      // after depthwise 3x3
__device__ float g_sumsq[B * CQK];                // per (b, ch) sum of squares
__device__ float g_gram[B * HEADS * 8 * 8];       // raw q.k^T per head
__device__ float g_M[B * C * C];                  // W_proj @ blockdiag(attn)

// ---------------- K_zero: clear reduction buffers ---------------------------
__global__ void k_zero() {
    int i = blockIdx.x * blockDim.x + threadIdx.x;
    if (i < B * CQK) g_sumsq[i] = 0.0f;
    if (i < B * HEADS * 64) g_gram[i] = 0.0f;
}

// ---------------- K0: fused 1x1 convs (qkv q/k chunks + m1 with BN fold) ----
// grid (HW/256, B), 256 threads, dyn smem = (192*64 + 256)*4 bytes
__global__ void k_pointwise(const float* __restrict__ x,
                            const float* __restrict__ w_qkv,
                            const float* __restrict__ b_qkv,
                            const float* __restrict__ w_m1,
                            const float* __restrict__ bn_g,
                            const float* __restrict__ bn_b,
                            const float* __restrict__ bn_m,
                            const float* __restrict__ bn_v) {
    extern __shared__ float sm[];
    float* sw     = sm;                 // 192*64 weights (128 qkv rows, 64 m1 rows)
    float* sbias  = sm + 192 * 64;      // 128
    float* sscale = sbias + 128;        // 64
    float* sshift = sscale + 64;        // 64
    int tid = threadIdx.x;
    for (int i = tid; i < 128 * 64; i += blockDim.x) sw[i] = w_qkv[i];
    for (int i = tid; i < 64 * 64;  i += blockDim.x) sw[128 * 64 + i] = w_m1[i];
    for (int i = tid; i < 128;      i += blockDim.x) sbias[i] = b_qkv[i];
    for (int i = tid; i < 64;       i += blockDim.x) {
        float s = bn_g[i] * rsqrtf(bn_v[i] + 1e-5f);
        sscale[i] = s;
        sshift[i] = bn_b[i] - bn_m[i] * s;
    }
    __syncthreads();

    int b = blockIdx.y;
    int p = blockIdx.x * blockDim.x + tid;
    const float* xb = x + (size_t)b * C * HW + p;

    float xv[64];
#pragma unroll
    for (int ic = 0; ic < 64; ic++) xv[ic] = xb[(size_t)ic * HW];

    float* qout = g_qk_pre + (size_t)b * CQK * HW + p;
    for (int oc = 0; oc < 128; oc++) {
        float acc = sbias[oc];
        const float* wr = sw + oc * 64;
#pragma unroll
        for (int ic = 0; ic < 64; ic++) acc = fmaf(wr[ic], xv[ic], acc);
        qout[(size_t)oc * HW] = acc;
    }
    float* yout = g_y + (size_t)b * C * HW + p;
    for (int oc = 0; oc < 64; oc++) {
        float acc = 0.0f;
        const float* wr = sw + (128 + oc) * 64;
#pragma unroll
        for (int ic = 0; ic < 64; ic++) acc = fmaf(wr[ic], xv[ic], acc);
        yout[(size_t)oc * HW] = acc * sscale[oc] + sshift[oc];
    }
}

// ---------------- K1: depthwise 3x3 (q,k channels) + sumsq reduction --------
// grid (HW/256, 128, B), 256 threads
__global__ void k_dw(const float* __restrict__ w_dw,
                     const float* __restrict__ b_dw) {
    int ch = blockIdx.y;
    int b  = blockIdx.z;
    int p  = blockIdx.x * 256 + threadIdx.x;
    int row = p >> 8, col = p & 255;
    const float* in = g_qk_pre + ((size_t)b * CQK + ch) * HW;

    float w[9];
#pragma unroll
    for (int i = 0; i < 9; i++) w[i] = __ldg(&w_dw[ch * 9 + i]);
    float acc = __ldg(&b_dw[ch]);
#pragma unroll
    for (int dy = -1; dy <= 1; dy++) {
        int r = row + dy;
        if (r < 0 || r > 255) continue;
#pragma unroll
        for (int dx = -1; dx <= 1; dx++) {
            int cc = col + dx;
            if (cc < 0 || cc > 255) continue;
            acc = fmaf(w[(dy + 1) * 3 + (dx + 1)], in[r * 256 + cc], acc);
        }
    }
    g_qk[((size_t)b * CQK + ch) * HW + p] = acc;

    // block-reduce sum of squares -> atomicAdd
    float sq = acc * acc;
#pragma unroll
    for (int off = 16; off; off >>= 1) sq += __shfl_xor_sync(0xffffffffu, sq, off);
    __shared__ float wsum[8];
    if ((threadIdx.x & 31) == 0) wsum[threadIdx.x >> 5] = sq;
    __syncthreads();
    if (threadIdx.x < 8) {
        float v = wsum[threadIdx.x];
#pragma unroll
        for (int off = 4; off; off >>= 1) v += __shfl_xor_sync(0xffu, v, off);
        if (threadIdx.x == 0) atomicAdd(&g_sumsq[b * CQK + ch], v);
    }
}

// ---------------- K2: raw Gram matrices per (b, head) -----------------------
// grid (32, B*HEADS), 256 threads
__global__ void k_gram() {
    int bh = blockIdx.y;
    int b = bh >> 3, h = bh & 7;
    const float* qbase = g_qk + (size_t)b * CQK * HW + (size_t)(h * 8) * HW;
    const float* kbase = g_qk + (size_t)b * CQK * HW + (size_t)(64 + h * 8) * HW;

    float acc[64];
#pragma unroll
    for (int i = 0; i < 64; i++) acc[i] = 0.0f;

    const int chunk = HW / 32;  // 2048
    int start = blockIdx.x * chunk;
    for (int p = start + threadIdx.x; p < start + chunk; p += 256) {
        float qv[8], kv[8];
#pragma unroll
        for (int i = 0; i < 8; i++) {
            qv[i] = qbase[(size_t)i * HW + p];
            kv[i] = kbase[(size_t)i * HW + p];
        }
#pragma unroll
        for (int i = 0; i < 8; i++)
#pragma unroll
            for (int j = 0; j < 8; j++)
                acc[i * 8 + j] = fmaf(qv[i], kv[j], acc[i * 8 + j]);
    }
#pragma unroll
    for (int t = 0; t < 64; t++) {
        float v = acc[t];
#pragma unroll
        for (int off = 16; off; off >>= 1) v += __shfl_xor_sync(0xffffffffu, v, off);
        if ((threadIdx.x & 31) == 0) atomicAdd(&g_gram[bh * 64 + t], v);
    }
}

// ---------------- K4: softmax(attn) then M_b = Wproj @ blockdiag(attn_b) ----
// 1 block, 256 threads
__global__ void k_attn(const float* __restrict__ w_proj,
                       const float* __restrict__ temperature) {
    __shared__ float attn[B * HEADS * 8 * 8];
    int tid = threadIdx.x;          // 256 rows = (b,h,i)
    int b = tid >> 6, h = (tid >> 3) & 7, i = tid & 7;

    float nq = fmaxf(sqrtf(g_sumsq[b * CQK + h * 8 + i]), 1e-12f);
    float temp = temperature[h];
    float row[8];
    float mx = -1e30f;
#pragma unroll
    for (int j = 0; j < 8; j++) {
        float nk = fmaxf(sqrtf(g_sumsq[b * CQK + 64 + h * 8 + j]), 1e-12f);
        float v = g_gram[((b * 8 + h) * 8 + i) * 8 + j] / (nq * nk) * temp;
        row[j] = v;
        mx = fmaxf(mx, v);
    }
    float s = 0.0f;
#pragma unroll
    for (int j = 0; j < 8; j++) { row[j] = expf(row[j] - mx); s += row[j]; }
    float inv = 1.0f / s;
#pragma unroll
    for (int j = 0; j < 8; j++) attn[((b * 8 + h) * 8 + i) * 8 + j] = row[j] * inv;
    __syncthreads();

    // M[b][oc][h*8+j] = sum_i wproj[oc][h*8+i] * attn[b][h][i][j]
    for (int e = tid; e < B * 64 * 64; e += 256) {
        int b2 = e >> 12, oc = (e >> 6) & 63, d = e & 63;
        int h2 = d >> 3, j = d & 7;
        float s2 = 0.0f;
#pragma unroll
        for (int i2 = 0; i2 < 8; i2++)
            s2 += w_proj[oc * 64 + h2 * 8 + i2] * attn[((b2 * 8 + h2) * 8 + i2) * 8 + j];
        g_M[e] = s2;
    }
}

// ---------------- K3: conv5x5 + sigmoid gate + fused (M @ v + bias) ---------
// grid (16, 16, B), 256 threads (16x16 tile), dyn smem ~145 KB
__global__ void k_conv5_out(const float* __restrict__ x,
                            const float* __restrict__ w_m2,
                            const float* __restrict__ b_proj,
                            float* __restrict__ out) {
    extern __shared__ float sm[];
    float* ysm = sm;            // 16ch * 20 * 20 = 6400
    float* wsm = ysm + 6400;    // 64oc * 16ic * 25 = 25600
    float* Msm = wsm + 25600;   // 64*64 = 4096
    float* bsm = Msm + 4096;    // 64

    int b = blockIdx.z;
    int tile_x = blockIdx.x * 16, tile_y = blockIdx.y * 16;
    int tid = threadIdx.x;
    int tx = tid & 15, ty = tid >> 4;

    for (int i = tid; i < 4096; i += 256) Msm[i] = g_M[b * 4096 + i];
    if (tid < 64) bsm[tid] = b_proj[tid];

    float acc[64];
#pragma unroll
    for (int i = 0; i < 64; i++) acc[i] = 0.0f;

    for (int icc = 0; icc < 4; icc++) {
        __syncthreads();
        // stage y halo tile for 16 input channels
        for (int i = tid; i < 16 * 20 * 20; i += 256) {
            int ic = i / 400;
            int rr = (i / 20) % 20;
            int cc = i % 20;
            int gy = tile_y - 2 + rr, gx = tile_x - 2 + cc;
            float v = 0.0f;
            if (gy >= 0 && gy < HDIM && gx >= 0 && gx < WDIM)
                v = g_y[((size_t)b * C + icc * 16 + ic) * HW + gy * WDIM + gx];
            ysm[i] = v;
        }
        // stage weights for this ic chunk
        for (int i = tid; i < 64 * 16 * 25; i += 256) {
            int oc = i / 400;
            int rem = i % 400;
            int ic = rem / 25, t = rem % 25;
            wsm[i] = w_m2[(oc * 64 + icc * 16 + ic) * 25 + t];
        }
        __syncthreads();

        for (int ic = 0; ic < 16; ic++) {
            float win[25];
#pragma unroll
            for (int dy = 0; dy < 5; dy++)
#pragma unroll
                for (int dx = 0; dx < 5; dx++)
                    win[dy * 5 + dx] = ysm[ic * 400 + (ty + dy) * 20 + (tx + dx)];
#pragma unroll
            for (int oc = 0; oc < 64; oc++) {
                const float* wr = wsm + (oc * 16 + ic) * 25;
#pragma unroll
                for (int t = 0; t < 25; t++) acc[oc] = fmaf(wr[t], win[t], acc[oc]);
            }
        }
    }

    // gate: v = x * (1 + sigmoid(conv))
    int p = (tile_y + ty) * WDIM + tile_x + tx;
    const float* xb = x + (size_t)b * C * HW + p;
    float vv[64];
#pragma unroll
    for (int d = 0; d < 64; d++) {
        float xval = xb[(size_t)d * HW];
        float sg = 1.0f / (1.0f + __expf(-acc[d]));
        vv[d] = xval * (1.0f + sg);
    }
    // epilogue: out[oc] = b_proj[oc] + sum_d M[b][oc][d] * vv[d]
    float* ob = out + (size_t)b * C * HW + p;
    for (int oc = 0; oc < 64; oc++) {
        float s = bsm[oc];
        const float* mr = Msm + oc * 64;
#pragma unroll
        for (int d = 0; d < 64; d++) s = fmaf(mr[d], vv[d], s);
        ob[(size_t)oc * HW] = s;
    }
}

// ---------------- launch --------------------------------------------------
extern "C" void kernel_launch(void* const* d_in, const int* in_sizes, int n_in,
                              void* d_out, int out_size) {
    const float* x      = (const float*)d_in[0];
    const float* w_qkv  = (const float*)d_in[1];
    const float* b_qkv  = (const float*)d_in[2];
    const float* w_dw   = (const float*)d_in[3];
    const float* b_dw   = (const float*)d_in[4];
    const float* w_proj = (const float*)d_in[5];
    const float* b_proj = (const float*)d_in[6];
    const float* temp   = (const float*)d_in[7];
    const float* w_m1   = (const float*)d_in[8];
    const float* bn_g   = (const float*)d_in[9];
    const float* bn_b   = (const float*)d_in[10];
    const float* bn_m   = (const float*)d_in[11];
    const float* bn_v   = (const float*)d_in[12];
    const float* w_m2   = (const float*)d_in[13];
    float* out = (float*)d_out;

    size_t smem_k0 = (size_t)(192 * 64 + 256) * sizeof(float);           // ~50 KB
    size_t smem_k3 = (size_t)(6400 + 25600 + 4096 + 64) * sizeof(float); // ~145 KB
    cudaFuncSetAttribute(k_pointwise, cudaFuncAttributeMaxDynamicSharedMemorySize,
                         (int)smem_k0);
    cudaFuncSetAttribute(k_conv5_out, cudaFuncAttributeMaxDynamicSharedMemorySize,
                         (int)smem_k3);

    k_zero<<<8, 256>>>();
    k_pointwise<<<dim3(HW / 256, B), 256, smem_k0>>>(x, w_qkv, b_qkv, w_m1,
                                                     bn_g, bn_b, bn_m, bn_v);
    k_dw<<<dim3(HW / 256, CQK, B), 256>>>(w_dw, b_dw);
    k_gram<<<dim3(32, B * HEADS), 256>>>();
    k_attn<<<1, 256>>>(w_proj, temp);
    k_conv5_out<<<dim3(16, 16, B), 256, smem_k3>>>(x, w_m2, b_proj, out);
}

// round 2
// speedup vs baseline: 3.8265x; 3.8265x over previous
#include <cuda_runtime.h>
#include <math.h>
#include <stdint.h>

#define B 4
#define C 64
#define CQK 128
#define HDIM 256
#define WDIM 256
#define HW 65536
#define HEADS 8

// ---------------- scratch (device globals; no allocations allowed) ----------
__device__ float g_qk_pre[(size_t)B * CQK * HW];  // qkv pre-depthwise, q+k only
__device__ float g_y[(size_t)B * C * HW];         // BN(m1(x)), tf32-rounded
__device__ float g_qk[(size_t)B * CQK * HW];      // after depthwise 3x3
__device__ float g_sumsq[B * CQK];                // per (b, ch) sum of squares
__device__ float g_gram[B * HEADS * 8 * 8];       // raw q.k^T per head
__device__ float g_M[B * C * C];                  // W_proj @ blockdiag(attn)
__device__ float g_Wt[25 * 64 * 64];              // w_m2 reordered [tap][ic][oc], tf32

// ---------------- helpers ---------------------------------------------------
__device__ __forceinline__ float to_tf32(float v) {
    uint32_t u;
    asm("cvt.rna.tf32.f32 %0, %1;" : "=r"(u) : "f"(v));
    return __uint_as_float(u);
}

__device__ __forceinline__ void mma_tf32(float* d, const uint32_t* a, const uint32_t* b) {
    asm volatile(
        "mma.sync.aligned.m16n8k8.row.col.f32.tf32.tf32.f32 "
        "{%0,%1,%2,%3}, {%4,%5,%6,%7}, {%8,%9}, {%0,%1,%2,%3};"
        : "+f"(d[0]), "+f"(d[1]), "+f"(d[2]), "+f"(d[3])
        : "r"(a[0]), "r"(a[1]), "r"(a[2]), "r"(a[3]), "r"(b[0]), "r"(b[1]));
}

__device__ __forceinline__ void cp_async16(uint32_t daddr, const void* src) {
    asm volatile("cp.async.cg.shared.global [%0], [%1], 16;" :: "r"(daddr), "l"(src));
}

// ---------------- K_zero: clear reduction buffers ---------------------------
__global__ void k_zero() {
    int i = blockIdx.x * blockDim.x + threadIdx.x;
    if (i < B * CQK) g_sumsq[i] = 0.0f;
    if (i < B * HEADS * 64) g_gram[i] = 0.0f;
}

// ---------------- K_wt: reorder m2 weights to [tap][ic][oc] (tf32) ----------
__global__ void k_wt(const float* __restrict__ w_m2) {
    int i = blockIdx.x * 256 + threadIdx.x;
    if (i < 25 * 4096) {
        int t = i / 4096;
        int rem = i & 4095;
        int ic = rem >> 6, oc = rem & 63;
        g_Wt[i] = to_tf32(w_m2[(oc * 64 + ic) * 25 + t]);
    }
}

// ---------------- K0: fused 1x1 convs (qkv q/k chunks + m1 with BN fold) ----
__global__ void k_pointwise(const float* __restrict__ x,
                            const float* __restrict__ w_qkv,
                            const float* __restrict__ b_qkv,
                            const float* __restrict__ w_m1,
                            const float* __restrict__ bn_g,
                            const float* __restrict__ bn_b,
                            const float* __restrict__ bn_m,
                            const float* __restrict__ bn_v) {
    extern __shared__ float sm[];
    float* sw     = sm;                 // 192*64
    float* sbias  = sm + 192 * 64;      // 128
    float* sscale = sbias + 128;        // 64
    float* sshift = sscale + 64;        // 64
    int tid = threadIdx.x;
    for (int i = tid; i < 128 * 64; i += blockDim.x) sw[i] = w_qkv[i];
    for (int i = tid; i < 64 * 64;  i += blockDim.x) sw[128 * 64 + i] = w_m1[i];
    for (int i = tid; i < 128;      i += blockDim.x) sbias[i] = b_qkv[i];
    for (int i = tid; i < 64;       i += blockDim.x) {
        float s = bn_g[i] * rsqrtf(bn_v[i] + 1e-5f);
        sscale[i] = s;
        sshift[i] = bn_b[i] - bn_m[i] * s;
    }
    __syncthreads();

    int b = blockIdx.y;
    int p = blockIdx.x * blockDim.x + tid;
    const float* xb = x + (size_t)b * C * HW + p;

    float xv[64];
#pragma unroll
    for (int ic = 0; ic < 64; ic++) xv[ic] = xb[(size_t)ic * HW];

    const float4* sw4 = (const float4*)sw;
    float* qout = g_qk_pre + (size_t)b * CQK * HW + p;
    for (int oc = 0; oc < 128; oc++) {
        float a = sbias[oc];
#pragma unroll
        for (int i = 0; i < 16; i++) {
            float4 w4 = sw4[oc * 16 + i];
            a = fmaf(w4.x, xv[4 * i + 0], a);
            a = fmaf(w4.y, xv[4 * i + 1], a);
            a = fmaf(w4.z, xv[4 * i + 2], a);
            a = fmaf(w4.w, xv[4 * i + 3], a);
        }
        qout[(size_t)oc * HW] = a;
    }
    float* yout = g_y + (size_t)b * C * HW + p;
    for (int oc = 0; oc < 64; oc++) {
        float a = 0.0f;
#pragma unroll
        for (int i = 0; i < 16; i++) {
            float4 w4 = sw4[(128 + oc) * 16 + i];
            a = fmaf(w4.x, xv[4 * i + 0], a);
            a = fmaf(w4.y, xv[4 * i + 1], a);
            a = fmaf(w4.z, xv[4 * i + 2], a);
            a = fmaf(w4.w, xv[4 * i + 3], a);
        }
        yout[(size_t)oc * HW] = to_tf32(a * sscale[oc] + sshift[oc]);
    }
}

// ---------------- K1: depthwise 3x3 (q,k channels) + sumsq reduction --------
__global__ void k_dw(const float* __restrict__ w_dw,
                     const float* __restrict__ b_dw) {
    int ch = blockIdx.y;
    int b  = blockIdx.z;
    int p  = blockIdx.x * 256 + threadIdx.x;
    int row = p >> 8, col = p & 255;
    const float* in = g_qk_pre + ((size_t)b * CQK + ch) * HW;

    float w[9];
#pragma unroll
    for (int i = 0; i < 9; i++) w[i] = __ldg(&w_dw[ch * 9 + i]);
    float acc = __ldg(&b_dw[ch]);
#pragma unroll
    for (int dy = -1; dy <= 1; dy++) {
        int r = row + dy;
        if (r < 0 || r > 255) continue;
#pragma unroll
        for (int dx = -1; dx <= 1; dx++) {
            int cc = col + dx;
            if (cc < 0 || cc > 255) continue;
            acc = fmaf(w[(dy + 1) * 3 + (dx + 1)], in[r * 256 + cc], acc);
        }
    }
    g_qk[((size_t)b * CQK + ch) * HW + p] = acc;

    float sq = acc * acc;
#pragma unroll
    for (int off = 16; off; off >>= 1) sq += __shfl_xor_sync(0xffffffffu, sq, off);
    __shared__ float wsum[8];
    if ((threadIdx.x & 31) == 0) wsum[threadIdx.x >> 5] = sq;
    __syncthreads();
    if (threadIdx.x < 8) {
        float v = wsum[threadIdx.x];
#pragma unroll
        for (int off = 4; off; off >>= 1) v += __shfl_xor_sync(0xffu, v, off);
        if (threadIdx.x == 0) atomicAdd(&g_sumsq[b * CQK + ch], v);
    }
}

// ---------------- K2: raw Gram matrices per (b, head) -----------------------
__global__ void k_gram() {
    int bh = blockIdx.y;
    int b = bh >> 3, h = bh & 7;
    const float* qbase = g_qk + (size_t)b * CQK * HW + (size_t)(h * 8) * HW;
    const float* kbase = g_qk + (size_t)b * CQK * HW + (size_t)(64 + h * 8) * HW;

    float acc[64];
#pragma unroll
    for (int i = 0; i < 64; i++) acc[i] = 0.0f;

    const int chunk = HW / 32;
    int start = blockIdx.x * chunk;
    for (int p = start + threadIdx.x; p < start + chunk; p += 256) {
        float qv[8], kv[8];
#pragma unroll
        for (int i = 0; i < 8; i++) {
            qv[i] = qbase[(size_t)i * HW + p];
            kv[i] = kbase[(size_t)i * HW + p];
        }
#pragma unroll
        for (int i = 0; i < 8; i++)
#pragma unroll
            for (int j = 0; j < 8; j++)
                acc[i * 8 + j] = fmaf(qv[i], kv[j], acc[i * 8 + j]);
    }
#pragma unroll
    for (int t = 0; t < 64; t++) {
        float v = acc[t];
#pragma unroll
        for (int off = 16; off; off >>= 1) v += __shfl_xor_sync(0xffffffffu, v, off);
        if ((threadIdx.x & 31) == 0) atomicAdd(&g_gram[bh * 64 + t], v);
    }
}

// ---------------- K4: softmax(attn) then M_b = Wproj @ blockdiag(attn_b) ----
__global__ void k_attn(const float* __restrict__ w_proj,
                       const float* __restrict__ temperature) {
    __shared__ float attn[B * HEADS * 8 * 8];
    int tid = threadIdx.x;
    int b = tid >> 6, h = (tid >> 3) & 7, i = tid & 7;

    float nq = fmaxf(sqrtf(g_sumsq[b * CQK + h * 8 + i]), 1e-12f);
    float temp = temperature[h];
    float row[8];
    float mx = -1e30f;
#pragma unroll
    for (int j = 0; j < 8; j++) {
        float nk = fmaxf(sqrtf(g_sumsq[b * CQK + 64 + h * 8 + j]), 1e-12f);
        float v = g_gram[((b * 8 + h) * 8 + i) * 8 + j] / (nq * nk) * temp;
        row[j] = v;
        mx = fmaxf(mx, v);
    }
    float s = 0.0f;
#pragma unroll
    for (int j = 0; j < 8; j++) { row[j] = expf(row[j] - mx); s += row[j]; }
    float inv = 1.0f / s;
#pragma unroll
    for (int j = 0; j < 8; j++) attn[((b * 8 + h) * 8 + i) * 8 + j] = row[j] * inv;
    __syncthreads();

    for (int e = tid; e < B * 64 * 64; e += 256) {
        int b2 = e >> 12, oc = (e >> 6) & 63, d = e & 63;
        int h2 = d >> 3, j = d & 7;
        float s2 = 0.0f;
#pragma unroll
        for (int i2 = 0; i2 < 8; i2++)
            s2 += w_proj[oc * 64 + h2 * 8 + i2] * attn[((b2 * 8 + h2) * 8 + i2) * 8 + j];
        g_M[e] = s2;
    }
}

// ---------------- K3: tf32 tensor-core conv5x5 + gate + fused epilogue ------
// grid (16, 16, B), 256 threads, ~156 KB smem
// Tile: 16x16 pixels. Per warp: 2 M-tiles (16 px each), 8 N-frags (64 oc).
#define YSTRIDE 408   // 20*20=400 padded; 408%32==24 -> conflict-free A gathers
#define WSTRIDE 72    // 64 oc padded;     72%32==8   -> conflict-free B loads
#define VSTRIDE 68    // 64 ch padded;     68%32==4   -> conflict-free A gathers

__global__ __launch_bounds__(256, 1)
void k_conv5_out(const float* __restrict__ x,
                 const float* __restrict__ b_proj,
                 float* __restrict__ out) {
    extern __shared__ float sm[];
    float* ysm = sm;                        // 64 * 408
    float* wsm = sm + 64 * YSTRIDE;         // 2 * 64 * 72 (double buffer)
    float* Msm = wsm + 2 * 64 * WSTRIDE;    // 64 * 72

    const int b = blockIdx.z;
    const int tx0 = blockIdx.x * 16, ty0 = blockIdx.y * 16;
    const int tid = threadIdx.x;
    const int w = tid >> 5, lane = tid & 31;
    const int g = lane >> 2, t4 = lane & 3;

    // stage y halo tile (already tf32-rounded in g_y)
    for (int i = tid; i < 64 * 400; i += 256) {
        int ic = i / 400;
        int rem = i - ic * 400;
        int r = rem / 20, cc = rem - r * 20;
        int gy = ty0 - 2 + r, gx = tx0 - 2 + cc;
        float v = 0.0f;
        if (gy >= 0 && gy < HDIM && gx >= 0 && gx < WDIM)
            v = g_y[(size_t)(b * 64 + ic) * HW + gy * WDIM + gx];
        ysm[ic * YSTRIDE + r * 20 + cc] = v;
    }

    // prefetch tap-0 weights via cp.async
    {
        uint32_t base = (uint32_t)__cvta_generic_to_shared(wsm);
        for (int i = tid * 4; i < 4096; i += 1024) {
            int k = i >> 6, oc = i & 63;
            cp_async16(base + (uint32_t)(k * WSTRIDE + oc) * 4u, g_Wt + i);
        }
        asm volatile("cp.async.commit_group;");
    }

    float acc[2][8][4];
#pragma unroll
    for (int m = 0; m < 2; m++)
#pragma unroll
        for (int n = 0; n < 8; n++)
#pragma unroll
            for (int j = 0; j < 4; j++) acc[m][n][j] = 0.0f;

    const uint32_t* ysmu = (const uint32_t*)ysm;

    for (int t = 0; t < 25; t++) {
        const float* wbuf = wsm + (t & 1) * (64 * WSTRIDE);
        if (t + 1 < 25) {
            float* nbuf = wsm + ((t + 1) & 1) * (64 * WSTRIDE);
            uint32_t base = (uint32_t)__cvta_generic_to_shared(nbuf);
            const float* src = g_Wt + (t + 1) * 4096;
            for (int i = tid * 4; i < 4096; i += 1024) {
                int k = i >> 6, oc = i & 63;
                cp_async16(base + (uint32_t)(k * WSTRIDE + oc) * 4u, src + i);
            }
            asm volatile("cp.async.commit_group;");
            asm volatile("cp.async.wait_group 1;");
        } else {
            asm volatile("cp.async.wait_group 0;");
        }
        __syncthreads();

        const int dy = t / 5, dx = t - dy * 5;
        const uint32_t* wbu = (const uint32_t*)wbuf;
        const int ro0 = (2 * w + dy) * 20 + dx + g;  // M-tile0 spatial offset

#pragma unroll
        for (int ks = 0; ks < 8; ks++) {
            int ic = ks * 8 + t4;
            int abase = ic * YSTRIDE + ro0;
            uint32_t a0[4], a1[4];
            a0[0] = ysmu[abase];
            a0[1] = ysmu[abase + 8];
            a0[2] = ysmu[abase + 4 * YSTRIDE];
            a0[3] = ysmu[abase + 4 * YSTRIDE + 8];
            a1[0] = ysmu[abase + 20];
            a1[1] = ysmu[abase + 28];
            a1[2] = ysmu[abase + 4 * YSTRIDE + 20];
            a1[3] = ysmu[abase + 4 * YSTRIDE + 28];
            int bbase = ic * WSTRIDE + g;
#pragma unroll
            for (int n = 0; n < 8; n++) {
                uint32_t bb[2];
                bb[0] = wbu[bbase + n * 8];
                bb[1] = wbu[bbase + 4 * WSTRIDE + n * 8];
                mma_tf32(acc[0][n], a0, bb);
                mma_tf32(acc[1][n], a1, bb);
            }
        }
        __syncthreads();
    }

    // ---- stage M^T (tf32) and gated values vv (tf32) ----
    for (int i = tid; i < 4096; i += 256) {
        int ch = i & 63;            // g_M layout: [oc][ch]
        int oc = i >> 6;
        Msm[ch * WSTRIDE + oc] = to_tf32(g_M[b * 4096 + i]);
    }
    float* vvsm = ysm;  // reuse (256 px * VSTRIDE)
#pragma unroll
    for (int m = 0; m < 2; m++) {
        int py = 2 * w + m;
        int gy = ty0 + py;
#pragma unroll
        for (int n = 0; n < 8; n++) {
#pragma unroll
            for (int j = 0; j < 4; j++) {
                int px = g + ((j >> 1) << 3);
                int ch = n * 8 + t4 * 2 + (j & 1);
                float xv = x[(size_t)(b * 64 + ch) * HW + gy * WDIM + tx0 + px];
                float a = acc[m][n][j];
                float sg = 1.0f / (1.0f + __expf(-a));
                vvsm[(py * 16 + px) * VSTRIDE + ch] = to_tf32(xv * (1.0f + sg));
                acc[m][n][j] = 0.0f;   // reuse accumulators for epilogue
            }
        }
    }
    __syncthreads();

    // ---- epilogue GEMM: out[px][oc] = sum_ch vv[px][ch] * M^T[ch][oc] ----
    const uint32_t* vvu = (const uint32_t*)vvsm;
    const uint32_t* Msu = (const uint32_t*)Msm;
    const int p0 = 32 * w + g;
#pragma unroll
    for (int ks = 0; ks < 8; ks++) {
        int ch = ks * 8 + t4;
        uint32_t a0[4], a1[4];
        a0[0] = vvu[p0 * VSTRIDE + ch];
        a0[1] = vvu[(p0 + 8) * VSTRIDE + ch];
        a0[2] = vvu[p0 * VSTRIDE + ch + 4];
        a0[3] = vvu[(p0 + 8) * VSTRIDE + ch + 4];
        a1[0] = vvu[(p0 + 16) * VSTRIDE + ch];
        a1[1] = vvu[(p0 + 24) * VSTRIDE + ch];
        a1[2] = vvu[(p0 + 16) * VSTRIDE + ch + 4];
        a1[3] = vvu[(p0 + 24) * VSTRIDE + ch + 4];
        int bbase = ch * WSTRIDE + g;
#pragma unroll
        for (int n = 0; n < 8; n++) {
            uint32_t bb[2];
            bb[0] = Msu[bbase + n * 8];
            bb[1] = Msu[bbase + 4 * WSTRIDE + n * 8];
            mma_tf32(acc[0][n], a0, bb);
            mma_tf32(acc[1][n], a1, bb);
        }
    }

    // ---- store ----
#pragma unroll
    for (int m = 0; m < 2; m++) {
        int gy = ty0 + 2 * w + m;
#pragma unroll
        for (int n = 0; n < 8; n++) {
#pragma unroll
            for (int j = 0; j < 4; j++) {
                int px = g + ((j >> 1) << 3);
                int oc = n * 8 + t4 * 2 + (j & 1);
                out[(size_t)(b * 64 + oc) * HW + gy * WDIM + tx0 + px] =
                    acc[m][n][j] + __ldg(&b_proj[oc]);
            }
        }
    }
}

// ---------------- launch --------------------------------------------------
extern "C" void kernel_launch(void* const* d_in, const int* in_sizes, int n_in,
                              void* d_out, int out_size) {
    const float* x      = (const float*)d_in[0];
    const float* w_qkv  = (const float*)d_in[1];
    const float* b_qkv  = (const float*)d_in[2];
    const float* w_dw   = (const float*)d_in[3];
    const float* b_dw   = (const float*)d_in[4];
    const float* w_proj = (const float*)d_in[5];
    const float* b_proj = (const float*)d_in[6];
    const float* temp   = (const float*)d_in[7];
    const float* w_m1   = (const float*)d_in[8];
    const float* bn_g   = (const float*)d_in[9];
    const float* bn_b   = (const float*)d_in[10];
    const float* bn_m   = (const float*)d_in[11];
    const float* bn_v   = (const float*)d_in[12];
    const float* w_m2   = (const float*)d_in[13];
    float* out = (float*)d_out;

    size_t smem_k0 = (size_t)(192 * 64 + 256) * sizeof(float);
    size_t smem_k3 = (size_t)(64 * YSTRIDE + 2 * 64 * WSTRIDE + 64 * WSTRIDE) * sizeof(float);
    cudaFuncSetAttribute(k_pointwise, cudaFuncAttributeMaxDynamicSharedMemorySize,
                         (int)smem_k0);
    cudaFuncSetAttribute(k_conv5_out, cudaFuncAttributeMaxDynamicSharedMemorySize,
                         (int)smem_k3);

    k_zero<<<8, 256>>>();
    k_wt<<<400, 256>>>(w_m2);
    k_pointwise<<<dim3(HW / 256, B), 256, smem_k0>>>(x, w_qkv, b_qkv, w_m1,
                                                     bn_g, bn_b, bn_m, bn_v);
    k_dw<<<dim3(HW / 256, CQK, B), 256>>>(w_dw, b_dw);
    k_gram<<<dim3(32, B * HEADS), 256>>>();
    k_attn<<<1, 256>>>(w_proj, temp);
    k_conv5_out<<<dim3(16, 16, B), 256, smem_k3>>>(x, b_proj, out);
}

// round 3
// speedup vs baseline: 5.9142x; 1.5456x over previous
#include <cuda_runtime.h>
#include <math.h>
#include <stdint.h>

#define B 4
#define C 64
#define CQK 128
#define HDIM 256
#define WDIM 256
#define HW 65536
#define HEADS 8

// ---------------- scratch ----------------------------------------------------
__device__ float g_qk_pre[(size_t)B * CQK * HW];  // qkv pre-depthwise (q+k)
__device__ float g_y[(size_t)B * C * HW];         // BN(m1(x)), tf32-rounded
__device__ float g_sumsq[B * CQK];
__device__ float g_gram[B * HEADS * 8 * 8];
__device__ float g_M[B * C * C];                  // W_proj @ blockdiag(attn)
__device__ float g_Wt[25 * 64 * 64];              // w_m2 [tap][ic][oc], tf32

// ---------------- helpers -----------------------------------------------------
__device__ __forceinline__ float to_tf32(float v) {
    uint32_t u;
    asm("cvt.rna.tf32.f32 %0, %1;" : "=r"(u) : "f"(v));
    return __uint_as_float(u);
}

__device__ __forceinline__ void mma_tf32(float* d, const uint32_t* a, const uint32_t* b) {
    asm volatile(
        "mma.sync.aligned.m16n8k8.row.col.f32.tf32.tf32.f32 "
        "{%0,%1,%2,%3}, {%4,%5,%6,%7}, {%8,%9}, {%0,%1,%2,%3};"
        : "+f"(d[0]), "+f"(d[1]), "+f"(d[2]), "+f"(d[3])
        : "r"(a[0]), "r"(a[1]), "r"(a[2]), "r"(a[3]), "r"(b[0]), "r"(b[1]));
}

__device__ __forceinline__ void cp_async16(uint32_t daddr, const void* src) {
    asm volatile("cp.async.cg.shared.global [%0], [%1], 16;" :: "r"(daddr), "l"(src));
}

// ---------------- K_zero ------------------------------------------------------
__global__ void k_zero() {
    int i = blockIdx.x * blockDim.x + threadIdx.x;
    if (i < B * CQK) g_sumsq[i] = 0.0f;
    if (i < B * HEADS * 64) g_gram[i] = 0.0f;
}

// ---------------- K_wt: reorder m2 weights to [tap][ic][oc] (tf32) ------------
__global__ void k_wt(const float* __restrict__ w_m2) {
    int i = blockIdx.x * 256 + threadIdx.x;
    if (i < 25 * 4096) {
        int t = i / 4096;
        int rem = i & 4095;
        int ic = rem >> 6, oc = rem & 63;
        g_Wt[i] = to_tf32(w_m2[(oc * 64 + ic) * 25 + t]);
    }
}

// ---------------- K0: tf32-MMA fused 1x1 convs (qkv q/k + m1/BN) --------------
// grid (HW/128, B), 256 threads. M=128 px, N=192 oc, K=64 ic.
#define PSTR 136   // 128 px + 8 -> conflict-free A gathers
#define OSTR 200   // 192 oc + 8 -> conflict-free B loads

__global__ __launch_bounds__(256)
void k_pointwise(const float* __restrict__ x,
                 const float* __restrict__ w_qkv,
                 const float* __restrict__ b_qkv,
                 const float* __restrict__ w_m1,
                 const float* __restrict__ bn_g,
                 const float* __restrict__ bn_b,
                 const float* __restrict__ bn_m,
                 const float* __restrict__ bn_v) {
    extern __shared__ float sm[];
    float* xs     = sm;                  // 64 * 136
    float* ws     = xs + 64 * PSTR;      // 64 * 200
    float* sscale = ws + 64 * OSTR;      // 192
    float* sshift = sscale + 192;        // 192

    const int tid = threadIdx.x;
    const int b = blockIdx.y;
    const int p0 = blockIdx.x * 128;

    for (int i = tid; i < 128 * 64; i += 256) {
        int oc = i >> 6, ic = i & 63;
        ws[ic * OSTR + oc] = to_tf32(w_qkv[i]);
    }
    for (int i = tid; i < 64 * 64; i += 256) {
        int oc = i >> 6, ic = i & 63;
        ws[ic * OSTR + 128 + oc] = to_tf32(w_m1[i]);
    }
    for (int i = tid; i < 192; i += 256) {
        if (i < 128) { sscale[i] = 1.0f; sshift[i] = b_qkv[i]; }
        else {
            int cc = i - 128;
            float s = bn_g[cc] * rsqrtf(bn_v[cc] + 1e-5f);
            sscale[i] = s;
            sshift[i] = bn_b[cc] - bn_m[cc] * s;
        }
    }
    for (int i = tid * 4; i < 64 * 128; i += 1024) {
        int ic = i >> 7, px = i & 127;
        float4 v = *(const float4*)(x + (size_t)(b * 64 + ic) * HW + p0 + px);
        float* d = xs + ic * PSTR + px;
        d[0] = to_tf32(v.x); d[1] = to_tf32(v.y);
        d[2] = to_tf32(v.z); d[3] = to_tf32(v.w);
    }
    __syncthreads();

    const int w = tid >> 5, lane = tid & 31;
    const int g = lane >> 2, t4 = lane & 3;

    float acc[24][4];
#pragma unroll
    for (int n = 0; n < 24; n++)
#pragma unroll
        for (int j = 0; j < 4; j++) acc[n][j] = 0.0f;

    const uint32_t* xsu = (const uint32_t*)xs;
    const uint32_t* wsu = (const uint32_t*)ws;
    const int mrow = w * 16 + g;

#pragma unroll
    for (int ks = 0; ks < 8; ks++) {
        int ic = ks * 8 + t4;
        uint32_t a[4];
        a[0] = xsu[ic * PSTR + mrow];
        a[1] = xsu[ic * PSTR + mrow + 8];
        a[2] = xsu[(ic + 4) * PSTR + mrow];
        a[3] = xsu[(ic + 4) * PSTR + mrow + 8];
        int bb0 = ic * OSTR + g;
#pragma unroll
        for (int n = 0; n < 24; n++) {
            uint32_t bb[2];
            bb[0] = wsu[bb0 + n * 8];
            bb[1] = wsu[bb0 + 4 * OSTR + n * 8];
            mma_tf32(acc[n], a, bb);
        }
    }

#pragma unroll
    for (int n = 0; n < 24; n++) {
#pragma unroll
        for (int j = 0; j < 4; j++) {
            int oc = n * 8 + t4 * 2 + (j & 1);
            int px = p0 + w * 16 + g + ((j >> 1) << 3);
            float v = acc[n][j] * sscale[oc] + sshift[oc];
            if (oc < 128)
                g_qk_pre[(size_t)(b * 128 + oc) * HW + px] = v;
            else
                g_y[(size_t)(b * 64 + oc - 128) * HW + px] = to_tf32(v);
        }
    }
}

// ---------------- K1: fused depthwise3x3 + gram + sumsq -----------------------
// grid (8, 8, B*HEADS), 256 threads. Tile 32x32, 16 channels (8 q + 8 k).
__global__ __launch_bounds__(256)
void k_dwgram(const float* __restrict__ w_dw,
              const float* __restrict__ b_dw) {
    extern __shared__ float sm[];          // 16 * 1190 halo tiles
    float* wsm = sm + 16 * 1190;           // 144
    float* bsm = wsm + 144;                // 16

    const int bh = blockIdx.z;
    const int b = bh >> 3, h = bh & 7;
    const int tx0 = blockIdx.x * 32, ty0 = blockIdx.y * 32;
    const int tid = threadIdx.x;

    for (int i = tid; i < 144; i += 256) {
        int c16 = i / 9, t = i - c16 * 9;
        int ch = (c16 < 8) ? h * 8 + c16 : 64 + h * 8 + (c16 - 8);
        wsm[i] = w_dw[ch * 9 + t];
    }
    if (tid < 16) {
        int ch = (tid < 8) ? h * 8 + tid : 64 + h * 8 + (tid - 8);
        bsm[tid] = b_dw[ch];
    }
    for (int i = tid; i < 16 * 1156; i += 256) {
        int c16 = i / 1156;
        int rem = i - c16 * 1156;
        int r = rem / 34, cc = rem - r * 34;
        int gy = ty0 - 1 + r, gx = tx0 - 1 + cc;
        int ch = (c16 < 8) ? h * 8 + c16 : 64 + h * 8 + (c16 - 8);
        float v = 0.0f;
        if (gy >= 0 && gy < HDIM && gx >= 0 && gx < WDIM)
            v = g_qk_pre[((size_t)b * CQK + ch) * HW + gy * WDIM + gx];
        sm[c16 * 1190 + r * 35 + cc] = v;
    }
    __syncthreads();

    float gacc[64], ssq[16];
#pragma unroll
    for (int i = 0; i < 64; i++) gacc[i] = 0.0f;
#pragma unroll
    for (int i = 0; i < 16; i++) ssq[i] = 0.0f;

#pragma unroll
    for (int pp = 0; pp < 4; pp++) {
        int p = tid + pp * 256;
        int py = p >> 5, px = p & 31;
        float dv[16];
#pragma unroll
        for (int c16 = 0; c16 < 16; c16++) {
            const float* in = sm + c16 * 1190 + py * 35 + px;
            float a = bsm[c16];
#pragma unroll
            for (int dy = 0; dy < 3; dy++)
#pragma unroll
                for (int dx = 0; dx < 3; dx++)
                    a = fmaf(wsm[c16 * 9 + dy * 3 + dx], in[dy * 35 + dx], a);
            dv[c16] = a;
            ssq[c16] = fmaf(a, a, ssq[c16]);
        }
#pragma unroll
        for (int i = 0; i < 8; i++)
#pragma unroll
            for (int j = 0; j < 8; j++)
                gacc[i * 8 + j] = fmaf(dv[i], dv[8 + j], gacc[i * 8 + j]);
    }

    __syncthreads();   // smem reuse for reduction
    float* red = sm;
    const int w = tid >> 5, lane = tid & 31;
#pragma unroll
    for (int v = 0; v < 64; v++) {
        float s = gacc[v];
#pragma unroll
        for (int off = 16; off; off >>= 1) s += __shfl_xor_sync(0xffffffffu, s, off);
        if (lane == 0) red[w * 80 + v] = s;
    }
#pragma unroll
    for (int v = 0; v < 16; v++) {
        float s = ssq[v];
#pragma unroll
        for (int off = 16; off; off >>= 1) s += __shfl_xor_sync(0xffffffffu, s, off);
        if (lane == 0) red[w * 80 + 64 + v] = s;
    }
    __syncthreads();
    if (tid < 80) {
        float s = 0.0f;
#pragma unroll
        for (int w2 = 0; w2 < 8; w2++) s += red[w2 * 80 + tid];
        if (tid < 64) atomicAdd(&g_gram[bh * 64 + tid], s);
        else {
            int c16 = tid - 64;
            int ch = (c16 < 8) ? h * 8 + c16 : 64 + h * 8 + (c16 - 8);
            atomicAdd(&g_sumsq[b * CQK + ch], s);
        }
    }
}

// ---------------- K4: softmax + M_b = Wproj @ blockdiag(attn_b) ---------------
__global__ void k_attn(const float* __restrict__ w_proj,
                       const float* __restrict__ temperature) {
    __shared__ float attn[B * HEADS * 8 * 8];
    int tid = threadIdx.x;
    int b = tid >> 6, h = (tid >> 3) & 7, i = tid & 7;

    float nq = fmaxf(sqrtf(g_sumsq[b * CQK + h * 8 + i]), 1e-12f);
    float temp = temperature[h];
    float row[8];
    float mx = -1e30f;
#pragma unroll
    for (int j = 0; j < 8; j++) {
        float nk = fmaxf(sqrtf(g_sumsq[b * CQK + 64 + h * 8 + j]), 1e-12f);
        float v = g_gram[((b * 8 + h) * 8 + i) * 8 + j] / (nq * nk) * temp;
        row[j] = v;
        mx = fmaxf(mx, v);
    }
    float s = 0.0f;
#pragma unroll
    for (int j = 0; j < 8; j++) { row[j] = expf(row[j] - mx); s += row[j]; }
    float inv = 1.0f / s;
#pragma unroll
    for (int j = 0; j < 8; j++) attn[((b * 8 + h) * 8 + i) * 8 + j] = row[j] * inv;
    __syncthreads();

    for (int e = tid; e < B * 64 * 64; e += 256) {
        int b2 = e >> 12, oc = (e >> 6) & 63, d = e & 63;
        int h2 = d >> 3, j = d & 7;
        float s2 = 0.0f;
#pragma unroll
        for (int i2 = 0; i2 < 8; i2++)
            s2 += w_proj[oc * 64 + h2 * 8 + i2] * attn[((b2 * 8 + h2) * 8 + i2) * 8 + j];
        g_M[e] = s2;
    }
}

// ---------------- K3: tf32 conv5x5 (ic-chunked) + gate + epilogue -------------
#define YSTRIDE 408
#define WSTRIDE 72
#define VSTRIDE 68
#define WSM_OFF (32 * YSTRIDE)                 // 13056
#define MSM_OFF (WSM_OFF + 2 * 32 * WSTRIDE)   // 17664

__global__ __launch_bounds__(256, 2)
void k_conv5_out(const float* __restrict__ x,
                 const float* __restrict__ b_proj,
                 float* __restrict__ out) {
    extern __shared__ float sm[];
    float* ysm = sm;                 // 32 * 408
    float* wsm = sm + WSM_OFF;       // 2 * 32 * 72
    float* Msm = sm + MSM_OFF;       // 64 * 72

    const int b = blockIdx.z;
    const int tx0 = blockIdx.x * 16, ty0 = blockIdx.y * 16;
    const int tid = threadIdx.x;
    const int w = tid >> 5, lane = tid & 31;
    const int g = lane >> 2, t4 = lane & 3;

    for (int i = tid; i < 4096; i += 256) {
        int ch = i & 63, oc = i >> 6;                // g_M is [oc][ch]
        Msm[ch * WSTRIDE + oc] = to_tf32(g_M[b * 4096 + i]);
    }

    float acc[2][8][4];
#pragma unroll
    for (int m = 0; m < 2; m++)
#pragma unroll
        for (int n = 0; n < 8; n++)
#pragma unroll
            for (int j = 0; j < 4; j++) acc[m][n][j] = 0.0f;

    const uint32_t* ysmu = (const uint32_t*)ysm;

    for (int icc = 0; icc < 2; icc++) {
        // stage 32-channel halo
        for (int i = tid; i < 32 * 400; i += 256) {
            int ic = i / 400;
            int rem = i - ic * 400;
            int r = rem / 20, cc = rem - r * 20;
            int gy = ty0 - 2 + r, gx = tx0 - 2 + cc;
            float v = 0.0f;
            if (gy >= 0 && gy < HDIM && gx >= 0 && gx < WDIM)
                v = g_y[(size_t)(b * 64 + icc * 32 + ic) * HW + gy * WDIM + gx];
            ysm[ic * YSTRIDE + r * 20 + cc] = v;
        }
        // prefetch tap-0 weight chunk
        {
            uint32_t base = (uint32_t)__cvta_generic_to_shared(wsm);
            const float* src = g_Wt + icc * 2048;
            for (int i = tid * 4; i < 2048; i += 1024) {
                int k = i >> 6, oc = i & 63;
                cp_async16(base + (uint32_t)(k * WSTRIDE + oc) * 4u, src + i);
            }
            asm volatile("cp.async.commit_group;");
        }

        for (int t = 0; t < 25; t++) {
            const float* wbuf = wsm + (t & 1) * (32 * WSTRIDE);
            if (t + 1 < 25) {
                float* nbuf = wsm + ((t + 1) & 1) * (32 * WSTRIDE);
                uint32_t base = (uint32_t)__cvta_generic_to_shared(nbuf);
                const float* src = g_Wt + (t + 1) * 4096 + icc * 2048;
                for (int i = tid * 4; i < 2048; i += 1024) {
                    int k = i >> 6, oc = i & 63;
                    cp_async16(base + (uint32_t)(k * WSTRIDE + oc) * 4u, src + i);
                }
                asm volatile("cp.async.commit_group;");
                asm volatile("cp.async.wait_group 1;");
            } else {
                asm volatile("cp.async.wait_group 0;");
            }
            __syncthreads();

            const int dy = t / 5, dx = t - dy * 5;
            const uint32_t* wbu = (const uint32_t*)wbuf;
            const int ro0 = (2 * w + dy) * 20 + dx + g;

#pragma unroll
            for (int ks = 0; ks < 4; ks++) {
                int ic = ks * 8 + t4;
                int abase = ic * YSTRIDE + ro0;
                uint32_t a0[4], a1[4];
                a0[0] = ysmu[abase];
                a0[1] = ysmu[abase + 8];
                a0[2] = ysmu[abase + 4 * YSTRIDE];
                a0[3] = ysmu[abase + 4 * YSTRIDE + 8];
                a1[0] = ysmu[abase + 20];
                a1[1] = ysmu[abase + 28];
                a1[2] = ysmu[abase + 4 * YSTRIDE + 20];
                a1[3] = ysmu[abase + 4 * YSTRIDE + 28];
                int bbase = ic * WSTRIDE + g;
#pragma unroll
                for (int n = 0; n < 8; n++) {
                    uint32_t bb[2];
                    bb[0] = wbu[bbase + n * 8];
                    bb[1] = wbu[bbase + 4 * WSTRIDE + n * 8];
                    mma_tf32(acc[0][n], a0, bb);
                    mma_tf32(acc[1][n], a1, bb);
                }
            }
            __syncthreads();
        }
    }

    // ---- gate + stage vv (tf32) ----
    float* vvsm = sm;  // 256 px * VSTRIDE = 17408 < MSM_OFF
#pragma unroll
    for (int m = 0; m < 2; m++) {
        int py = 2 * w + m;
        int gy = ty0 + py;
#pragma unroll
        for (int n = 0; n < 8; n++) {
#pragma unroll
            for (int j = 0; j < 4; j++) {
                int px = g + ((j >> 1) << 3);
                int ch = n * 8 + t4 * 2 + (j & 1);
                float xv = x[(size_t)(b * 64 + ch) * HW + gy * WDIM + tx0 + px];
                float a = acc[m][n][j];
                float sg = 1.0f / (1.0f + __expf(-a));
                vvsm[(py * 16 + px) * VSTRIDE + ch] = to_tf32(xv * (1.0f + sg));
                acc[m][n][j] = 0.0f;
            }
        }
    }
    __syncthreads();

    // ---- epilogue GEMM: out[px][oc] = vv[px][:] @ M^T ----
    const uint32_t* vvu = (const uint32_t*)vvsm;
    const uint32_t* Msu = (const uint32_t*)Msm;
    const int p0 = 32 * w + g;
#pragma unroll
    for (int ks = 0; ks < 8; ks++) {
        int ch = ks * 8 + t4;
        uint32_t a0[4], a1[4];
        a0[0] = vvu[p0 * VSTRIDE + ch];
        a0[1] = vvu[(p0 + 8) * VSTRIDE + ch];
        a0[2] = vvu[p0 * VSTRIDE + ch + 4];
        a0[3] = vvu[(p0 + 8) * VSTRIDE + ch + 4];
        a1[0] = vvu[(p0 + 16) * VSTRIDE + ch];
        a1[1] = vvu[(p0 + 24) * VSTRIDE + ch];
        a1[2] = vvu[(p0 + 16) * VSTRIDE + ch + 4];
        a1[3] = vvu[(p0 + 24) * VSTRIDE + ch + 4];
        int bbase = ch * WSTRIDE + g;
#pragma unroll
        for (int n = 0; n < 8; n++) {
            uint32_t bb[2];
            bb[0] = Msu[bbase + n * 8];
            bb[1] = Msu[bbase + 4 * WSTRIDE + n * 8];
            mma_tf32(acc[0][n], a0, bb);
            mma_tf32(acc[1][n], a1, bb);
        }
    }

#pragma unroll
    for (int m = 0; m < 2; m++) {
        int gy = ty0 + 2 * w + m;
#pragma unroll
        for (int n = 0; n < 8; n++) {
#pragma unroll
            for (int j = 0; j < 4; j++) {
                int px = g + ((j >> 1) << 3);
                int oc = n * 8 + t4 * 2 + (j & 1);
                out[(size_t)(b * 64 + oc) * HW + gy * WDIM + tx0 + px] =
                    acc[m][n][j] + __ldg(&b_proj[oc]);
            }
        }
    }
}

// ---------------- launch ------------------------------------------------------
extern "C" void kernel_launch(void* const* d_in, const int* in_sizes, int n_in,
                              void* d_out, int out_size) {
    const float* x      = (const float*)d_in[0];
    const float* w_qkv  = (const float*)d_in[1];
    const float* b_qkv  = (const float*)d_in[2];
    const float* w_dw   = (const float*)d_in[3];
    const float* b_dw   = (const float*)d_in[4];
    const float* w_proj = (const float*)d_in[5];
    const float* b_proj = (const float*)d_in[6];
    const float* temp   = (const float*)d_in[7];
    const float* w_m1   = (const float*)d_in[8];
    const float* bn_g   = (const float*)d_in[9];
    const float* bn_b   = (const float*)d_in[10];
    const float* bn_m   = (const float*)d_in[11];
    const float* bn_v   = (const float*)d_in[12];
    const float* w_m2   = (const float*)d_in[13];
    float* out = (float*)d_out;

    size_t smem_k0 = (size_t)(64 * PSTR + 64 * OSTR + 384) * sizeof(float);   // ~87.5 KB
    size_t smem_dg = (size_t)(16 * 1190 + 160) * sizeof(float);               // ~76.8 KB
    size_t smem_k3 = (size_t)(MSM_OFF + 64 * WSTRIDE) * sizeof(float);        // ~89 KB
    cudaFuncSetAttribute(k_pointwise, cudaFuncAttributeMaxDynamicSharedMemorySize,
                         (int)smem_k0);
    cudaFuncSetAttribute(k_dwgram, cudaFuncAttributeMaxDynamicSharedMemorySize,
                         (int)smem_dg);
    cudaFuncSetAttribute(k_conv5_out, cudaFuncAttributeMaxDynamicSharedMemorySize,
                         (int)smem_k3);

    k_zero<<<8, 256>>>();
    k_wt<<<400, 256>>>(w_m2);
    k_pointwise<<<dim3(HW / 128, B), 256, smem_k0>>>(x, w_qkv, b_qkv, w_m1,
                                                     bn_g, bn_b, bn_m, bn_v);
    k_dwgram<<<dim3(8, 8, B * HEADS), 256, smem_dg>>>(w_dw, b_dw);
    k_attn<<<1, 256>>>(w_proj, temp);
    k_conv5_out<<<dim3(16, 16, B), 256, smem_k3>>>(x, b_proj, out);
}